// round 2
// baseline (speedup 1.0000x reference)
#include <cuda_runtime.h>
#include <math.h>

// Problem constants: N=8, R=256, IN=64, OUT=64, MODE=32
// kx mode list (64 entries): k<32 -> kx=k ; k>=32 -> kx=192+k (224..255)

// ---------------- device scratch ----------------
__device__ float g_T1[128 * 256];             // fwd h-DFT:  [kxc=2k+p][h]
__device__ float g_T2[64 * 512];              // fwd w-DFT:  [kyp=2ky+p][w | 256+w]
__device__ float g_T4[512 * 128];             // inv h-DFT:  [hp=2h+p][kxp=2k+p]
__device__ float g_T5[256 * 64];              // inv w-DFT:  [w][kyp]
__device__ float g_X1[(size_t)8 * 128 * 256 * 64];  // [n][kxc][w][i]   (67MB)
__device__ float g_X2[(size_t)8 * 64 * 64 * 64];    // [n][kx][kyp][i]  (8.4MB)
__device__ float g_F [(size_t)8 * 128 * 32 * 64];   // [n][kxp][ky][o]  (8.4MB)
__device__ float g_G [(size_t)8 * 512 * 2048];      // [n][hp][ky*64+o] (33.5MB)

__device__ __forceinline__ float silu_f(float t) {
    return t / (1.0f + __expf(-t));
}

// ---------------- twiddle init (runs every launch; deterministic) ----------------
__global__ void k_init() {
    int t = blockIdx.x * blockDim.x + threadIdx.x;   // 16384 threads
    {
        // T1: e^{-i 2pi kx h / 256}: row 2k = cos, row 2k+1 = -sin
        int k = t >> 8, h = t & 255;
        int kx = (k < 32) ? k : 192 + k;
        float s, c;
        sincospif((float)((kx * h) & 255) * (1.0f / 128.0f), &s, &c);
        g_T1[(2 * k) * 256 + h]     = c;
        g_T1[(2 * k + 1) * 256 + h] = -s;
    }
    if (t < 8192) {
        // T2: X2re = sum (X1re*c + X1im*s); X2im = sum (X1im*c - X1re*s)
        int ky = t >> 8, w = t & 255;
        float s, c;
        sincospif((float)((ky * w) & 255) * (1.0f / 128.0f), &s, &c);
        g_T2[(2 * ky) * 512 + w]           = c;
        g_T2[(2 * ky) * 512 + 256 + w]     = s;
        g_T2[(2 * ky + 1) * 512 + w]       = -s;
        g_T2[(2 * ky + 1) * 512 + 256 + w] = c;
    }
    {
        // T4: e^{+i 2pi kx h/256}: Gre = Fre*c - Fim*s ; Gim = Fre*s + Fim*c
        int h = t >> 6, k = t & 63;
        int kx = (k < 32) ? k : 192 + k;
        float s, c;
        sincospif((float)((kx * h) & 255) * (1.0f / 128.0f), &s, &c);
        g_T4[(2 * h) * 128 + 2 * k]         = c;
        g_T4[(2 * h) * 128 + 2 * k + 1]     = -s;
        g_T4[(2 * h + 1) * 128 + 2 * k]     = s;
        g_T4[(2 * h + 1) * 128 + 2 * k + 1] = c;
    }
    if (t < 8192) {
        // T5: y[w] = sum_ky c_ky * (Gre*cos - Gim*sin), c_0=1 else 2
        int w = t >> 5, ky = t & 31;
        float s, c;
        sincospif((float)((ky * w) & 255) * (1.0f / 128.0f), &s, &c);
        float f = (ky == 0) ? 1.0f : 2.0f;
        g_T5[w * 64 + 2 * ky]     = f * c;
        g_T5[w * 64 + 2 * ky + 1] = -f * s;
    }
}

// ---------------- residual: d_out = x @ res_w + res_b ----------------
// block: 256 pixels x 64 outs, 256 threads, 8x8 register tile. dynamic smem.
__global__ void __launch_bounds__(256) k_resid(const float* __restrict__ x,
                                               const float* __restrict__ rw,
                                               const float* __restrict__ rb,
                                               float* __restrict__ out) {
    extern __shared__ float sm[];
    float(*As)[260] = (float(*)[260])sm;            // [64 k][256 m(+pad)]
    float(*Bs)[68]  = (float(*)[68])(sm + 64 * 260); // [64 k][64 o(+pad)]
    float* bb = sm + 64 * 260 + 64 * 68;
    int tid = threadIdx.x;
    const float* xb = x + (size_t)blockIdx.x * 16384;
#pragma unroll
    for (int q = 0; q < 16; q++) {
        int f4 = tid + q * 256;
        int m = f4 >> 4, j = f4 & 15;
        float4 v = *(const float4*)(xb + m * 64 + j * 4);
        As[j * 4 + 0][m] = v.x; As[j * 4 + 1][m] = v.y;
        As[j * 4 + 2][m] = v.z; As[j * 4 + 3][m] = v.w;
    }
#pragma unroll
    for (int q = 0; q < 4; q++) {
        int f4 = tid + q * 256;
        int k = f4 >> 4, j = f4 & 15;
        *(float4*)&Bs[k][j * 4] = *(const float4*)(rw + k * 64 + j * 4);
    }
    if (tid < 64) bb[tid] = rb[tid];
    __syncthreads();
    int r0 = (tid >> 3) * 8, c0 = (tid & 7) * 8;
    float acc[8][8];
#pragma unroll
    for (int i = 0; i < 8; i++)
#pragma unroll
        for (int j = 0; j < 8; j++) acc[i][j] = bb[c0 + j];
#pragma unroll 4
    for (int k = 0; k < 64; k++) {
        float a[8], b[8];
        *(float4*)(a)     = *(float4*)&As[k][r0];
        *(float4*)(a + 4) = *(float4*)&As[k][r0 + 4];
        *(float4*)(b)     = *(float4*)&Bs[k][c0];
        *(float4*)(b + 4) = *(float4*)&Bs[k][c0 + 4];
#pragma unroll
        for (int i = 0; i < 8; i++)
#pragma unroll
            for (int j = 0; j < 8; j++) acc[i][j] += a[i] * b[j];
    }
    float* ob = out + (size_t)blockIdx.x * 16384;
#pragma unroll
    for (int i = 0; i < 8; i++) {
        int m = r0 + i;
        *(float4*)(ob + m * 64 + c0)     = make_float4(acc[i][0], acc[i][1], acc[i][2], acc[i][3]);
        *(float4*)(ob + m * 64 + c0 + 4) = make_float4(acc[i][4], acc[i][5], acc[i][6], acc[i][7]);
    }
}

// ---------------- S1: X1[n][kxc][w*64+i] = T1 @ x[n]  (M=128,K=256,N=16384) ----------------
__global__ void __launch_bounds__(256) k_s1(const float* __restrict__ x) {
    __shared__ float As[16][132];   // [kk][m=kxc]
    __shared__ float Bs[16][128];   // [kk][col]
    int tid = threadIdx.x;
    int n = blockIdx.y;
    int colbase = blockIdx.x * 128;
    const float* B = x + (size_t)n * (256 * 16384);
    float acc[8][8] = {};
    int r0 = (tid >> 4) * 8, c0 = (tid & 15) * 8;
    for (int kc = 0; kc < 256; kc += 16) {
#pragma unroll
        for (int q = 0; q < 2; q++) {
            int f4 = tid + q * 256;
            int m = f4 >> 2, j = f4 & 3;
            float4 v = *(const float4*)(g_T1 + m * 256 + kc + j * 4);
            As[j * 4 + 0][m] = v.x; As[j * 4 + 1][m] = v.y;
            As[j * 4 + 2][m] = v.z; As[j * 4 + 3][m] = v.w;
        }
#pragma unroll
        for (int q = 0; q < 2; q++) {
            int f4 = tid + q * 256;
            int kk = f4 >> 5, c4 = f4 & 31;
            *(float4*)&Bs[kk][c4 * 4] =
                *(const float4*)(B + (size_t)(kc + kk) * 16384 + colbase + c4 * 4);
        }
        __syncthreads();
#pragma unroll 4
        for (int k = 0; k < 16; k++) {
            float a[8], b[8];
            *(float4*)(a)     = *(float4*)&As[k][r0];
            *(float4*)(a + 4) = *(float4*)&As[k][r0 + 4];
            *(float4*)(b)     = *(float4*)&Bs[k][c0];
            *(float4*)(b + 4) = *(float4*)&Bs[k][c0 + 4];
#pragma unroll
            for (int i = 0; i < 8; i++)
#pragma unroll
                for (int j = 0; j < 8; j++) acc[i][j] += a[i] * b[j];
        }
        __syncthreads();
    }
    float* C = g_X1 + (size_t)n * 128 * 16384 + colbase;
#pragma unroll
    for (int i = 0; i < 8; i++) {
        int row = r0 + i;
        *(float4*)(C + (size_t)row * 16384 + c0)     = make_float4(acc[i][0], acc[i][1], acc[i][2], acc[i][3]);
        *(float4*)(C + (size_t)row * 16384 + c0 + 4) = make_float4(acc[i][4], acc[i][5], acc[i][6], acc[i][7]);
    }
}

// ---------------- S2: per (n,kx): X2[kyp][i] = T2[64][512] @ X1panel[512][64] ----------------
__global__ void __launch_bounds__(64) k_s2() {
    __shared__ float As[16][68];    // [kk][kyp]
    __shared__ float Bs[16][64];    // [kk][i]
    int tid = threadIdx.x;
    int kx = blockIdx.x & 63, n = blockIdx.x >> 6;
    const float* B = g_X1 + (size_t)(n * 128 + 2 * kx) * 16384;  // [512][64] contiguous
    float acc[8][8] = {};
    int r0 = (tid >> 3) * 8, c0 = (tid & 7) * 8;
    for (int kc = 0; kc < 512; kc += 16) {
#pragma unroll
        for (int q = 0; q < 4; q++) {
            int f4 = tid + q * 64;       // 256 = 64m * 4j
            int m = f4 >> 2, j = f4 & 3;
            float4 v = *(const float4*)(g_T2 + m * 512 + kc + j * 4);
            As[j * 4 + 0][m] = v.x; As[j * 4 + 1][m] = v.y;
            As[j * 4 + 2][m] = v.z; As[j * 4 + 3][m] = v.w;
        }
#pragma unroll
        for (int q = 0; q < 4; q++) {
            int f4 = tid + q * 64;       // 256 f4 = 1024 floats contiguous
            *(float4*)&Bs[0][f4 * 4] = *(const float4*)(B + kc * 64 + f4 * 4);
        }
        __syncthreads();
#pragma unroll 4
        for (int k = 0; k < 16; k++) {
            float a[8], b[8];
            *(float4*)(a)     = *(float4*)&As[k][r0];
            *(float4*)(a + 4) = *(float4*)&As[k][r0 + 4];
            *(float4*)(b)     = *(float4*)&Bs[k][c0];
            *(float4*)(b + 4) = *(float4*)&Bs[k][c0 + 4];
#pragma unroll
            for (int i = 0; i < 8; i++)
#pragma unroll
                for (int j = 0; j < 8; j++) acc[i][j] += a[i] * b[j];
        }
        __syncthreads();
    }
    float* C = g_X2 + (size_t)(n * 64 + kx) * 4096;  // [kyp][i]
#pragma unroll
    for (int i = 0; i < 8; i++) {
        *(float4*)(C + (r0 + i) * 64 + c0)     = make_float4(acc[i][0], acc[i][1], acc[i][2], acc[i][3]);
        *(float4*)(C + (r0 + i) * 64 + c0 + 4) = make_float4(acc[i][4], acc[i][5], acc[i][6], acc[i][7]);
    }
}

// ---------------- S3: mode channel mix (complex), scale by 1/65536 ----------------
__global__ void __launch_bounds__(256) k_s3(const float* __restrict__ w0,
                                            const float* __restrict__ w1) {
    __shared__ float Wre[64][64], Wim[64][64];
    __shared__ float Xre[8][64], Xim[8][64];
    int tid = threadIdx.x;
    int ky = blockIdx.x & 31, k = blockIdx.x >> 5;
    const float* W = (k < 32) ? (w0 + (size_t)(k * 32 + ky) * 4096 * 2)
                              : (w1 + (size_t)((k - 32) * 32 + ky) * 4096 * 2);
#pragma unroll
    for (int q = 0; q < 16; q++) {
        int e = tid + q * 256;          // i*64+o
        float2 v = *(const float2*)(W + (size_t)e * 2);
        Wre[e >> 6][e & 63] = v.x;
        Wim[e >> 6][e & 63] = v.y;
    }
#pragma unroll
    for (int q = 0; q < 2; q++) {
        int e = tid + q * 256;          // n*64+i
        int n = e >> 6, i = e & 63;
        Xre[n][i] = g_X2[((size_t)(n * 64 + k) * 64 + 2 * ky) * 64 + i];
        Xim[n][i] = g_X2[((size_t)(n * 64 + k) * 64 + 2 * ky + 1) * 64 + i];
    }
    __syncthreads();
    const float sc = 1.0f / 65536.0f;   // fwd ortho 1/256 * inv ortho 1/256
#pragma unroll
    for (int q = 0; q < 2; q++) {
        int e = tid + q * 256;
        int n = e >> 6, o = e & 63;
        float fre = 0.0f, fim = 0.0f;
#pragma unroll 8
        for (int i = 0; i < 64; i++) {
            float xr = Xre[n][i], xi = Xim[n][i];
            float wr = Wre[i][o], wi = Wim[i][o];
            fre += xr * wr - xi * wi;
            fim += xr * wi + xi * wr;
        }
        g_F[((size_t)(n * 128 + 2 * k) * 32 + ky) * 64 + o]     = fre * sc;
        g_F[((size_t)(n * 128 + 2 * k + 1) * 32 + ky) * 64 + o] = fim * sc;
    }
}

// ---------------- S4: per n: G[512 hp][2048] = T4[512][128] @ F[n][128][2048] ----------------
__global__ void __launch_bounds__(256) k_s4() {
    __shared__ float As[16][132];
    __shared__ float Bs[16][128];
    int tid = threadIdx.x;
    int colbase = blockIdx.x * 128;
    int m0 = blockIdx.y * 128;
    int n = blockIdx.z;
    const float* B = g_F + (size_t)n * 128 * 2048;
    float acc[8][8] = {};
    int r0 = (tid >> 4) * 8, c0 = (tid & 15) * 8;
    for (int kc = 0; kc < 128; kc += 16) {
#pragma unroll
        for (int q = 0; q < 2; q++) {
            int f4 = tid + q * 256;
            int m = f4 >> 2, j = f4 & 3;
            float4 v = *(const float4*)(g_T4 + (size_t)(m0 + m) * 128 + kc + j * 4);
            As[j * 4 + 0][m] = v.x; As[j * 4 + 1][m] = v.y;
            As[j * 4 + 2][m] = v.z; As[j * 4 + 3][m] = v.w;
        }
#pragma unroll
        for (int q = 0; q < 2; q++) {
            int f4 = tid + q * 256;
            int kk = f4 >> 5, c4 = f4 & 31;
            *(float4*)&Bs[kk][c4 * 4] =
                *(const float4*)(B + (size_t)(kc + kk) * 2048 + colbase + c4 * 4);
        }
        __syncthreads();
#pragma unroll 4
        for (int k = 0; k < 16; k++) {
            float a[8], b[8];
            *(float4*)(a)     = *(float4*)&As[k][r0];
            *(float4*)(a + 4) = *(float4*)&As[k][r0 + 4];
            *(float4*)(b)     = *(float4*)&Bs[k][c0];
            *(float4*)(b + 4) = *(float4*)&Bs[k][c0 + 4];
#pragma unroll
            for (int i = 0; i < 8; i++)
#pragma unroll
                for (int j = 0; j < 8; j++) acc[i][j] += a[i] * b[j];
        }
        __syncthreads();
    }
    float* C = g_G + (size_t)n * 512 * 2048 + colbase;
#pragma unroll
    for (int i = 0; i < 8; i++) {
        int row = m0 + r0 + i;
        *(float4*)(C + (size_t)row * 2048 + c0)     = make_float4(acc[i][0], acc[i][1], acc[i][2], acc[i][3]);
        *(float4*)(C + (size_t)row * 2048 + c0 + 4) = make_float4(acc[i][4], acc[i][5], acc[i][6], acc[i][7]);
    }
}

// ---------------- S5: per (n,h): y[w][o] = T5[256][64] @ G[64 kyp][64 o], + res, silu ----------------
__global__ void __launch_bounds__(256) k_s5(float* __restrict__ out) {
    extern __shared__ float sm[];
    float(*As)[260] = (float(*)[260])sm;             // [64 kyp][256 w(+pad)]
    float(*Bs)[68]  = (float(*)[68])(sm + 64 * 260);  // [64 kyp][64 o(+pad)]
    int tid = threadIdx.x;
    int h = blockIdx.x & 255, n = blockIdx.x >> 8;
#pragma unroll
    for (int q = 0; q < 16; q++) {
        int f4 = tid + q * 256;          // 4096 f4s of T5 (transpose load)
        int w = f4 >> 4, j = f4 & 15;
        float4 v = *(const float4*)(g_T5 + w * 64 + j * 4);
        As[j * 4 + 0][w] = v.x; As[j * 4 + 1][w] = v.y;
        As[j * 4 + 2][w] = v.z; As[j * 4 + 3][w] = v.w;
    }
    const float* G = g_G + (size_t)(n * 256 + h) * 4096;  // [p][ky][o]
#pragma unroll
    for (int q = 0; q < 4; q++) {
        int e4 = tid + q * 256;          // 1024 f4s
        int p = e4 >> 9, ky = (e4 >> 4) & 31, j = e4 & 15;
        float4 v = *(const float4*)(G + p * 2048 + ky * 64 + j * 4);
        *(float4*)&Bs[2 * ky + p][j * 4] = v;
    }
    __syncthreads();
    int r0 = (tid >> 3) * 8, c0 = (tid & 7) * 8;
    float acc[8][8] = {};
#pragma unroll 4
    for (int k = 0; k < 64; k++) {
        float a[8], b[8];
        *(float4*)(a)     = *(float4*)&As[k][r0];
        *(float4*)(a + 4) = *(float4*)&As[k][r0 + 4];
        *(float4*)(b)     = *(float4*)&Bs[k][c0];
        *(float4*)(b + 4) = *(float4*)&Bs[k][c0 + 4];
#pragma unroll
        for (int i = 0; i < 8; i++)
#pragma unroll
            for (int j = 0; j < 8; j++) acc[i][j] += a[i] * b[j];
    }
    float* ob = out + (size_t)(n * 256 + h) * 16384;   // [w][o], currently holds residual
#pragma unroll
    for (int i = 0; i < 8; i++) {
        int w = r0 + i;
        float4 rv0 = *(float4*)(ob + w * 64 + c0);
        float4 rv1 = *(float4*)(ob + w * 64 + c0 + 4);
        float4 o0, o1;
        o0.x = silu_f(acc[i][0] + rv0.x); o0.y = silu_f(acc[i][1] + rv0.y);
        o0.z = silu_f(acc[i][2] + rv0.z); o0.w = silu_f(acc[i][3] + rv0.w);
        o1.x = silu_f(acc[i][4] + rv1.x); o1.y = silu_f(acc[i][5] + rv1.y);
        o1.z = silu_f(acc[i][6] + rv1.z); o1.w = silu_f(acc[i][7] + rv1.w);
        *(float4*)(ob + w * 64 + c0)     = o0;
        *(float4*)(ob + w * 64 + c0 + 4) = o1;
    }
}

// ---------------- launch ----------------
extern "C" void kernel_launch(void* const* d_in, const int* in_sizes, int n_in,
                              void* d_out, int out_size) {
    const float* x  = (const float*)d_in[0];
    const float* w0 = (const float*)d_in[1];
    const float* w1 = (const float*)d_in[2];
    const float* rw = (const float*)d_in[3];
    const float* rb = (const float*)d_in[4];
    float* out = (float*)d_out;

    const int SMEM_BIG = (64 * 260 + 64 * 68 + 64) * 4;   // 84224 bytes
    cudaFuncSetAttribute(k_resid, cudaFuncAttributeMaxDynamicSharedMemorySize, SMEM_BIG);
    cudaFuncSetAttribute(k_s5,    cudaFuncAttributeMaxDynamicSharedMemorySize, SMEM_BIG);

    k_init<<<64, 256>>>();
    k_resid<<<2048, 256, SMEM_BIG>>>(x, rw, rb, out);
    dim3 g1(128, 8);
    k_s1<<<g1, 256>>>(x);
    k_s2<<<512, 64>>>();
    k_s3<<<2048, 256>>>(w0, w1);
    dim3 g4(16, 4, 8);
    k_s4<<<g4, 256>>>();
    k_s5<<<2048, 256, SMEM_BIG>>>(out);
}